// round 13
// baseline (speedup 1.0000x reference)
// R13: sync-free fusions — LN1 inlined into FF A-path; outproj+scatter folded into LN2(l=1)
#include <cuda_runtime.h>
#include <cuda_bf16.h>
#include <cstdint>

#define NSTEP 16
#define NB 128
#define NE 512
#define NH 8
#define NIN 256
#define NOUT 128
#define NMEM 32769
#define NLAY 2

#define OFF_WIN 0
#define OFF_IPW 131072
#define OFF_AOW 1703936
#define OFF_FFW 2228224
#define WTOT    2752512
#define CONV_TOT 3276800      // WTOT + 16*128*256 (seq)

// gemm smem geometry (bf16 elements)
#define GS_ROW    72          // 64 data + 8 pad (144B stride, 16B aligned)
#define GS_MAT    (64 * GS_ROW)
#define GS_BUF    (4 * GS_MAT)
#define GS_BYTES  (2 * GS_BUF * 2)     // 73728 B dynamic smem

// epilogue / A-path modes
#define EP_NONE 0
#define EP_SC0  2     // X gemm: also scatter rows m<NB into h slot 0
#define EP_LNA  3     // FF gemm: A = LN1(hsrc + psrc) built inline (K must be 512)

typedef __nv_bfloat16 bf16;

// ---- scratch ----
__device__ float g_X  [NSTEP * NB * NE];
__device__ float g_h  [NB * NSTEP * NE];
__device__ float g_qkv[NB * NSTEP * 3 * NE];
__device__ float g_tmp [NB * NSTEP * NE];     // proj output
__device__ float g_tmp2[NB * NSTEP * NE];     // FF output
__device__ __align__(16) bf16 g_hh[NB * NSTEP * NE];
__device__ __align__(16) bf16 g_hl[NB * NSTEP * NE];
__device__ __align__(16) bf16 g_ah[NB * NSTEP * NE];
__device__ __align__(16) bf16 g_al[NB * NSTEP * NE];
__device__ __align__(16) bf16 g_sh[NSTEP * NB * NIN];
__device__ __align__(16) bf16 g_sl[NSTEP * NB * NIN];
__device__ __align__(16) bf16 g_wh[WTOT];
__device__ __align__(16) bf16 g_wl[WTOT];

__device__ __forceinline__ uint32_t smem_u32(const void* p) {
    uint32_t a;
    asm("{ .reg .u64 t; cvta.to.shared.u64 t, %1; cvt.u32.u64 %0, t; }" : "=r"(a) : "l"(p));
    return a;
}

#define CP16(dst, src) \
    asm volatile("cp.async.cg.shared.global [%0], [%1], 16;" :: "r"(dst), "l"(src))
#define CP_COMMIT() asm volatile("cp.async.commit_group;")
#define CP_WAIT(n)  asm volatile("cp.async.wait_group %0;" :: "n"(n))

#define LDM4(r, addr) \
    asm volatile("ldmatrix.sync.aligned.m8n8.x4.shared.b16 {%0,%1,%2,%3}, [%4];" \
        : "=r"((r)[0]), "=r"((r)[1]), "=r"((r)[2]), "=r"((r)[3]) : "r"(addr))

#define MMA(d, a, b) \
    asm volatile("mma.sync.aligned.m16n8k16.row.col.f32.bf16.bf16.f32 " \
        "{%0,%1,%2,%3}, {%4,%5,%6,%7}, {%8,%9}, {%0,%1,%2,%3};" \
        : "+f"((d)[0]), "+f"((d)[1]), "+f"((d)[2]), "+f"((d)[3]) \
        : "r"((a)[0]), "r"((a)[1]), "r"((a)[2]), "r"((a)[3]), "r"((b)[0]), "r"((b)[1]))

#define STS128U(addr, v) \
    asm volatile("st.shared.v4.b32 [%0], {%1,%2,%3,%4};" \
        :: "r"(addr), "r"((v).x), "r"((v).y), "r"((v).z), "r"((v).w) : "memory")

__device__ __forceinline__ void split_store(size_t d, float v)
{
    bf16 h = __float2bfloat16(v);
    g_hh[d] = h;
    g_hl[d] = __float2bfloat16(v - __bfloat162float(h));
}

__device__ __forceinline__ uint32_t pk2(bf16 a, bf16 b) {
    return ((uint32_t)__bfloat16_as_ushort(b) << 16) | (uint32_t)__bfloat16_as_ushort(a);
}

// LN-transform 8 values and pack into bf16 hi/lo uint4s
__device__ __forceinline__ void ln_build8(
    float4 ha, float4 hb, float4 pa, float4 pb, float mu, float inv,
    float4 sa, float4 sb, float4 ba, float4 bb, uint4& Hv, uint4& Lv)
{
    float v0 = (ha.x + pa.x - mu) * inv * sa.x + ba.x;
    float v1 = (ha.y + pa.y - mu) * inv * sa.y + ba.y;
    float v2 = (ha.z + pa.z - mu) * inv * sa.z + ba.z;
    float v3 = (ha.w + pa.w - mu) * inv * sa.w + ba.w;
    float v4 = (hb.x + pb.x - mu) * inv * sb.x + bb.x;
    float v5 = (hb.y + pb.y - mu) * inv * sb.y + bb.y;
    float v6 = (hb.z + pb.z - mu) * inv * sb.z + bb.z;
    float v7 = (hb.w + pb.w - mu) * inv * sb.w + bb.w;
    bf16 h0 = __float2bfloat16(v0), h1 = __float2bfloat16(v1);
    bf16 h2 = __float2bfloat16(v2), h3 = __float2bfloat16(v3);
    bf16 h4 = __float2bfloat16(v4), h5 = __float2bfloat16(v5);
    bf16 h6 = __float2bfloat16(v6), h7 = __float2bfloat16(v7);
    Hv.x = pk2(h0, h1); Hv.y = pk2(h2, h3); Hv.z = pk2(h4, h5); Hv.w = pk2(h6, h7);
    Lv.x = pk2(__float2bfloat16(v0 - __bfloat162float(h0)), __float2bfloat16(v1 - __bfloat162float(h1)));
    Lv.y = pk2(__float2bfloat16(v2 - __bfloat162float(h2)), __float2bfloat16(v3 - __bfloat162float(h3)));
    Lv.z = pk2(__float2bfloat16(v4 - __bfloat162float(h4)), __float2bfloat16(v5 - __bfloat162float(h5)));
    Lv.w = pk2(__float2bfloat16(v6 - __bfloat162float(h6)), __float2bfloat16(v7 - __bfloat162float(h7)));
}

__device__ __forceinline__ float4 ld4(const float* p) { return *(const float4*)p; }

// ======================= tensor-core GEMM (64x64 tile, BK=64, cp.async) =====
// C[m,n] = sum_k A[m,k]*(Wh+Wl)[n,k] + bias[n]
//   EP_NONE/EP_SC0: A = (Ah+Al) bf16 pair, cp.async pipeline (3-term split)
//   EP_LNA:         A = LN1(hsrc + psrc) built inline (stats prologue, K==512)
__global__ __launch_bounds__(256) void gemm_tc_k(
    const bf16* __restrict__ Ah, const bf16* __restrict__ Al,
    const bf16* __restrict__ Wh, const bf16* __restrict__ Wl,
    const float* __restrict__ bias, float* __restrict__ C,
    int N, int K, int L, int slotA, int slotC,
    int mode, const float* __restrict__ sc, const float* __restrict__ bi,
    const float* __restrict__ hsrc, const float* __restrict__ psrc)
{
    extern __shared__ __align__(16) bf16 sm[];
    __shared__ float s_mu[64], s_iv[64];
    const uint32_t sbase = smem_u32(sm);

    const int tid  = threadIdx.x;
    const int warp = tid >> 5;
    const int lane = tid & 31;
    const int bm = blockIdx.y << 6;
    const int bn = blockIdx.x << 6;

    const int r0  = tid >> 3;
    const int r1  = 32 + r0;
    const int k16 = tid & 7;

    const int gm0 = bm + r0, gm1 = bm + r1;
    const int ab0 = gm0 / L, ab1 = gm1 / L;
    const size_t aoff0 = (size_t)(ab0 * slotA + (gm0 - ab0 * L)) * K + k16 * 8;
    const size_t aoff1 = (size_t)(ab1 * slotA + (gm1 - ab1 * L)) * K + k16 * 8;
    const size_t woff0 = (size_t)(bn + r0) * K + k16 * 8;
    const size_t woff1 = (size_t)(bn + r1) * K + k16 * 8;

    const uint32_t dA0 = sbase + (0 * GS_MAT + r0 * GS_ROW + k16 * 8) * 2;
    const uint32_t dA1 = sbase + (0 * GS_MAT + r1 * GS_ROW + k16 * 8) * 2;
    const uint32_t dB0 = sbase + (1 * GS_MAT + r0 * GS_ROW + k16 * 8) * 2;
    const uint32_t dB1 = sbase + (1 * GS_MAT + r1 * GS_ROW + k16 * 8) * 2;
    const uint32_t dW0 = sbase + (2 * GS_MAT + r0 * GS_ROW + k16 * 8) * 2;
    const uint32_t dW1 = sbase + (2 * GS_MAT + r1 * GS_ROW + k16 * 8) * 2;
    const uint32_t dV0 = sbase + (3 * GS_MAT + r0 * GS_ROW + k16 * 8) * 2;
    const uint32_t dV1 = sbase + (3 * GS_MAT + r1 * GS_ROW + k16 * 8) * 2;

    const int warpM = (warp >> 1) << 4;
    const int warpN = (warp & 1) << 5;
    const int aRow = (lane & 15);
    const int aKof = (lane >> 4) << 3;
    const uint32_t adrAh = sbase + (0 * GS_MAT + (warpM + aRow) * GS_ROW + aKof) * 2;
    const uint32_t adrAl = sbase + (1 * GS_MAT + (warpM + aRow) * GS_ROW + aKof) * 2;
    const int bRow = (lane & 7) + ((lane >> 4) << 3);
    const int bKof = ((lane >> 3) & 1) << 3;
    const uint32_t adrWh0 = sbase + (2 * GS_MAT + (warpN + bRow) * GS_ROW + bKof) * 2;
    const uint32_t adrWh1 = adrWh0 + 16 * GS_ROW * 2;
    const uint32_t adrWl0 = sbase + (3 * GS_MAT + (warpN + bRow) * GS_ROW + bKof) * 2;
    const uint32_t adrWl1 = adrWl0 + 16 * GS_ROW * 2;

    float acc[4][4];
    #pragma unroll
    for (int nt = 0; nt < 4; nt++)
        #pragma unroll
        for (int j = 0; j < 4; j++) acc[nt][j] = 0.f;

    const int nc = K >> 6;
    float mu0 = 0.f, iv0 = 0.f, mu1v = 0.f, iv1v = 0.f;

    if (mode == EP_LNA) {
        // W-only pipeline; A built inline with LN1
        CP16(dW0, Wh + woff0); CP16(dW1, Wh + woff1);
        CP16(dV0, Wl + woff0); CP16(dV1, Wl + woff1);
        CP_COMMIT();
        // row stats (all inputs finalized at kernel entry; no cross-CTA sync)
        for (int rr = warp; rr < 64; rr += 8) {
            int m = bm + rr; int bb = m / L; int ii = m - bb * L;
            size_t ro = (size_t)(bb * slotA + ii) * K;
            float s = 0.f, q = 0.f;
            #pragma unroll
            for (int j = 0; j < 16; j++) {
                int col = j * 32 + lane;
                float v = hsrc[ro + col] + psrc[ro + col];
                s += v; q += v * v;
            }
            #pragma unroll
            for (int o = 16; o > 0; o >>= 1) {
                s += __shfl_xor_sync(0xffffffffu, s, o);
                q += __shfl_xor_sync(0xffffffffu, q, o);
            }
            if (lane == 0) {
                float mu = s * (1.f / 512.f);
                s_mu[rr] = mu;
                s_iv[rr] = rsqrtf(q * (1.f / 512.f) - mu * mu + 1e-5f);
            }
        }
        __syncthreads();
        mu0 = s_mu[r0]; iv0 = s_iv[r0]; mu1v = s_mu[r1]; iv1v = s_iv[r1];
        // build A chunk 0 into buffer 0
        {
            const int gc = k16 * 8;
            float4 sa = ld4(sc + gc), sb = ld4(sc + gc + 4);
            float4 ba = ld4(bi + gc), bb = ld4(bi + gc + 4);
            uint4 H, Lv;
            ln_build8(ld4(hsrc + aoff0), ld4(hsrc + aoff0 + 4),
                      ld4(psrc + aoff0), ld4(psrc + aoff0 + 4),
                      mu0, iv0, sa, sb, ba, bb, H, Lv);
            STS128U(dA0, H); STS128U(dB0, Lv);
            ln_build8(ld4(hsrc + aoff1), ld4(hsrc + aoff1 + 4),
                      ld4(psrc + aoff1), ld4(psrc + aoff1 + 4),
                      mu1v, iv1v, sa, sb, ba, bb, H, Lv);
            STS128U(dA1, H); STS128U(dB1, Lv);
        }

        for (int c = 0; c < nc; c++) {
            const uint32_t bufo = (c & 1) ? (uint32_t)(GS_BUF * 2) : 0u;
            if (c + 1 < nc) {
                const uint32_t nbo = ((c + 1) & 1) ? (uint32_t)(GS_BUF * 2) : 0u;
                const int ko = (c + 1) << 6;
                CP16(dW0 + nbo, Wh + woff0 + ko); CP16(dW1 + nbo, Wh + woff1 + ko);
                CP16(dV0 + nbo, Wl + woff0 + ko); CP16(dV1 + nbo, Wl + woff1 + ko);
                CP_COMMIT();
                CP_WAIT(1);
            } else {
                CP_WAIT(0);
            }
            __syncthreads();

            // prefetch A-source rows for chunk c+1 (consumed after MMA)
            float4 Xh0a, Xh0b, Xp0a, Xp0b, Xh1a, Xh1b, Xp1a, Xp1b, Ysa, Ysb, Yba, Ybb;
            if (c + 1 < nc) {
                const int cb = (c + 1) << 6;
                Xh0a = ld4(hsrc + aoff0 + cb); Xh0b = ld4(hsrc + aoff0 + cb + 4);
                Xp0a = ld4(psrc + aoff0 + cb); Xp0b = ld4(psrc + aoff0 + cb + 4);
                Xh1a = ld4(hsrc + aoff1 + cb); Xh1b = ld4(hsrc + aoff1 + cb + 4);
                Xp1a = ld4(psrc + aoff1 + cb); Xp1b = ld4(psrc + aoff1 + cb + 4);
                const int gc = cb + k16 * 8;
                Ysa = ld4(sc + gc); Ysb = ld4(sc + gc + 4);
                Yba = ld4(bi + gc); Ybb = ld4(bi + gc + 4);
            }

            #pragma unroll
            for (int ks = 0; ks < 4; ks++) {
                const uint32_t kb = bufo + ks * 32;
                uint32_t ah[4], al[4];
                LDM4(ah, adrAh + kb);
                LDM4(al, adrAl + kb);
                uint32_t bh[4][2], bl[4][2];
                {
                    uint32_t t[4];
                    LDM4(t, adrWh0 + kb);
                    bh[0][0] = t[0]; bh[0][1] = t[1]; bh[1][0] = t[2]; bh[1][1] = t[3];
                    LDM4(t, adrWh1 + kb);
                    bh[2][0] = t[0]; bh[2][1] = t[1]; bh[3][0] = t[2]; bh[3][1] = t[3];
                    LDM4(t, adrWl0 + kb);
                    bl[0][0] = t[0]; bl[0][1] = t[1]; bl[1][0] = t[2]; bl[1][1] = t[3];
                    LDM4(t, adrWl1 + kb);
                    bl[2][0] = t[0]; bl[2][1] = t[1]; bl[3][0] = t[2]; bl[3][1] = t[3];
                }
                #pragma unroll
                for (int nt = 0; nt < 4; nt++) {
                    MMA(acc[nt], ah, bh[nt]);
                    MMA(acc[nt], ah, bl[nt]);
                    MMA(acc[nt], al, bh[nt]);
                }
            }

            if (c + 1 < nc) {
                const uint32_t nbo = ((c + 1) & 1) ? (uint32_t)(GS_BUF * 2) : 0u;
                uint4 H, Lv;
                ln_build8(Xh0a, Xh0b, Xp0a, Xp0b, mu0, iv0, Ysa, Ysb, Yba, Ybb, H, Lv);
                STS128U(dA0 + nbo, H); STS128U(dB0 + nbo, Lv);
                ln_build8(Xh1a, Xh1b, Xp1a, Xp1b, mu1v, iv1v, Ysa, Ysb, Yba, Ybb, H, Lv);
                STS128U(dA1 + nbo, H); STS128U(dB1 + nbo, Lv);
            }
            __syncthreads();
        }
    } else {
        // bf16 A via cp.async (R10 path)
        CP16(dA0, Ah + aoff0); CP16(dA1, Ah + aoff1);
        CP16(dB0, Al + aoff0); CP16(dB1, Al + aoff1);
        CP16(dW0, Wh + woff0); CP16(dW1, Wh + woff1);
        CP16(dV0, Wl + woff0); CP16(dV1, Wl + woff1);
        CP_COMMIT();

        for (int c = 0; c < nc; c++) {
            const uint32_t bufo = (c & 1) ? (uint32_t)(GS_BUF * 2) : 0u;
            if (c + 1 < nc) {
                const uint32_t nbo = ((c + 1) & 1) ? (uint32_t)(GS_BUF * 2) : 0u;
                const int ko = (c + 1) << 6;
                CP16(dA0 + nbo, Ah + aoff0 + ko); CP16(dA1 + nbo, Ah + aoff1 + ko);
                CP16(dB0 + nbo, Al + aoff0 + ko); CP16(dB1 + nbo, Al + aoff1 + ko);
                CP16(dW0 + nbo, Wh + woff0 + ko); CP16(dW1 + nbo, Wh + woff1 + ko);
                CP16(dV0 + nbo, Wl + woff0 + ko); CP16(dV1 + nbo, Wl + woff1 + ko);
                CP_COMMIT();
                CP_WAIT(1);
            } else {
                CP_WAIT(0);
            }
            __syncthreads();

            #pragma unroll
            for (int ks = 0; ks < 4; ks++) {
                const uint32_t kb = bufo + ks * 32;
                uint32_t ah[4], al[4];
                LDM4(ah, adrAh + kb);
                LDM4(al, adrAl + kb);
                uint32_t bh[4][2], bl[4][2];
                {
                    uint32_t t[4];
                    LDM4(t, adrWh0 + kb);
                    bh[0][0] = t[0]; bh[0][1] = t[1]; bh[1][0] = t[2]; bh[1][1] = t[3];
                    LDM4(t, adrWh1 + kb);
                    bh[2][0] = t[0]; bh[2][1] = t[1]; bh[3][0] = t[2]; bh[3][1] = t[3];
                    LDM4(t, adrWl0 + kb);
                    bl[0][0] = t[0]; bl[0][1] = t[1]; bl[1][0] = t[2]; bl[1][1] = t[3];
                    LDM4(t, adrWl1 + kb);
                    bl[2][0] = t[0]; bl[2][1] = t[1]; bl[3][0] = t[2]; bl[3][1] = t[3];
                }
                #pragma unroll
                for (int nt = 0; nt < 4; nt++) {
                    MMA(acc[nt], ah, bh[nt]);
                    MMA(acc[nt], ah, bl[nt]);
                    MMA(acc[nt], al, bh[nt]);
                }
            }
            __syncthreads();
        }
    }

    // ---- epilogue ----
    const int cn = bn + warpN + ((lane & 3) << 1);
    #pragma unroll
    for (int half = 0; half < 2; half++) {
        const int m = bm + warpM + (lane >> 2) + half * 8;
        const int b = m / L;
        const int i = m - b * L;
        float* cp = C + (size_t)(b * slotC + i) * N + cn;
        #pragma unroll
        for (int nt = 0; nt < 4; nt++) {
            float2 o;
            o.x = acc[nt][half * 2 + 0] + bias[cn + nt * 8];
            o.y = acc[nt][half * 2 + 1] + bias[cn + nt * 8 + 1];
            *(float2*)(cp + nt * 8) = o;
            if (mode == EP_SC0 && m < NB) {
                size_t d = (size_t)m * NSTEP * NE + cn + nt * 8;
                g_h[d] = o.x; g_h[d + 1] = o.y;
                split_store(d, o.x); split_store(d + 1, o.y);
            }
        }
    }
}

// ======================= fp32 -> bf16 hi/lo (all weights + seq) =======================
__global__ void conv_all_k(const float* __restrict__ Win, const float* __restrict__ ipw,
                           const float* __restrict__ aow, const float* __restrict__ ffw,
                           const float* __restrict__ seq)
{
    const int nth = gridDim.x * 256;
    for (int idx = blockIdx.x * 256 + threadIdx.x; idx < CONV_TOT; idx += nth) {
        if (idx < WTOT) {
            float x;
            if (idx < OFF_IPW)      x = Win[idx];
            else if (idx < OFF_AOW) x = ipw[idx - OFF_IPW];
            else if (idx < OFF_FFW) x = aow[idx - OFF_AOW];
            else                    x = ffw[idx - OFF_FFW];
            bf16 h = __float2bfloat16(x);
            g_wh[idx] = h;
            g_wl[idx] = __float2bfloat16(x - __bfloat162float(h));
        } else {
            int i2 = idx - WTOT;
            float x = seq[i2];
            bf16 h = __float2bfloat16(x);
            g_sh[i2] = h;
            g_sl[i2] = __float2bfloat16(x - __bfloat162float(h));
        }
    }
}

__device__ __forceinline__ void scatter_one(int t, int j)
{
    int b = j >> 9, e = j & 511;
    float x = g_X[((size_t)t * NB + b) * NE + e];
    size_t d = ((size_t)b * NSTEP + t) * NE + e;
    g_h[d] = x;
    split_store(d, x);
}

// ---- per (batch, head) attention; writes att as bf16 hi/lo ----
__global__ __launch_bounds__(256) void attn_k(int seqL)
{
    __shared__ float q_s[16][64], k_s[16][64], v_s[16][64];
    __shared__ float p_s[16][17];
    int blk = blockIdx.x; int b = blk >> 3; int hh = blk & 7;
    int tid = threadIdx.x;
    const float* base = g_qkv + (size_t)b * NSTEP * 1536 + hh * 64;
    for (int e = tid; e < 1024; e += 256) {
        int i = e >> 6, d = e & 63;
        if (i < seqL) {
            const float* p = base + (size_t)i * 1536 + d;
            q_s[i][d] = p[0];
            k_s[i][d] = p[512];
            v_s[i][d] = p[1024];
        }
    }
    __syncthreads();
    int si = tid >> 4, sj = tid & 15;
    if (si < seqL && sj < seqL) {
        float s = 0.f;
        #pragma unroll
        for (int d = 0; d < 64; d++) s += q_s[si][d] * k_s[sj][d];
        p_s[si][sj] = s * 0.125f;
    }
    __syncthreads();
    if (tid < seqL) {
        float mx = -1e30f;
        for (int j = 0; j < seqL; j++) mx = fmaxf(mx, p_s[tid][j]);
        float sum = 0.f;
        for (int j = 0; j < seqL; j++) { float e = expf(p_s[tid][j] - mx); p_s[tid][j] = e; sum += e; }
        float inv = 1.f / sum;
        for (int j = 0; j < seqL; j++) p_s[tid][j] *= inv;
    }
    __syncthreads();
    int qi = tid >> 4, d0 = (tid & 15) << 2;
    if (qi < seqL) {
        float o[4] = {0, 0, 0, 0};
        for (int j = 0; j < seqL; j++) {
            float p = p_s[qi][j];
            o[0] += p * v_s[j][d0];     o[1] += p * v_s[j][d0 + 1];
            o[2] += p * v_s[j][d0 + 2]; o[3] += p * v_s[j][d0 + 3];
        }
        size_t d = ((size_t)b * NSTEP + qi) * NE + hh * 64 + d0;
        #pragma unroll
        for (int k = 0; k < 4; k++) {
            bf16 h = __float2bfloat16(o[k]);
            g_ah[d + k] = h;
            g_al[d + k] = __float2bfloat16(o[k] - __bfloat162float(h));
        }
    }
}

// ======================= LN2 (recomputes LN1 chain) + fused outproj/scatter ==
// h_new = LN2( LN1(h + P) + F );  rows r < NB*Lq.
// do_out: CTAs with i==t also compute out[t,b,:] = h_new_row @ Wout^T + b_out.
// r >= NB*Lq (64 extra CTAs, only when scatter needed): scatter x_{t+1} into slot t+1.
__global__ __launch_bounds__(256) void ln2_k(
    const float* __restrict__ s1v, const float* __restrict__ b1v,
    const float* __restrict__ s2v, const float* __restrict__ b2v,
    const float* __restrict__ P, const float* __restrict__ F,
    int Lq, int t, int do_out,
    const float* __restrict__ Wout, const float* __restrict__ b_out,
    float* __restrict__ out)
{
    const int tid = threadIdx.x;
    const int r = blockIdx.x;
    const int nrows = NB * Lq;
    if (r >= nrows) {
        for (int e = (r - nrows) * 256 + tid; e < NB * NE; e += 64 * 256)
            scatter_one(t + 1, e);
        return;
    }
    __shared__ float shs[8], shq[8];
    __shared__ float mu1_s, iv1_s, mu2_s, iv2_s;
    __shared__ __align__(16) float rowbuf[512];
    const int b = r / Lq, i = r - b * Lq;
    const size_t rowo = ((size_t)b * NSTEP + i) * NE;
    const int lane = tid & 31, w = tid >> 5;

    float a0 = g_h[rowo + tid]       + P[rowo + tid];
    float a1 = g_h[rowo + tid + 256] + P[rowo + tid + 256];
    {
        float s = a0 + a1, q = a0 * a0 + a1 * a1;
        #pragma unroll
        for (int o = 16; o > 0; o >>= 1) {
            s += __shfl_down_sync(0xffffffffu, s, o);
            q += __shfl_down_sync(0xffffffffu, q, o);
        }
        if (lane == 0) { shs[w] = s; shq[w] = q; }
        __syncthreads();
        if (tid == 0) {
            float ts = 0, tq = 0;
            #pragma unroll
            for (int k = 0; k < 8; k++) { ts += shs[k]; tq += shq[k]; }
            float mu = ts * (1.f / 512.f);
            mu1_s = mu; iv1_s = rsqrtf(tq * (1.f / 512.f) - mu * mu + 1e-5f);
        }
        __syncthreads();
    }
    float v10 = (a0 - mu1_s) * iv1_s * s1v[tid]       + b1v[tid];
    float v11 = (a1 - mu1_s) * iv1_s * s1v[tid + 256] + b1v[tid + 256];
    float y0 = v10 + F[rowo + tid];
    float y1 = v11 + F[rowo + tid + 256];
    __syncthreads();     // protect shs/shq reuse
    {
        float s = y0 + y1, q = y0 * y0 + y1 * y1;
        #pragma unroll
        for (int o = 16; o > 0; o >>= 1) {
            s += __shfl_down_sync(0xffffffffu, s, o);
            q += __shfl_down_sync(0xffffffffu, q, o);
        }
        if (lane == 0) { shs[w] = s; shq[w] = q; }
        __syncthreads();
        if (tid == 0) {
            float ts = 0, tq = 0;
            #pragma unroll
            for (int k = 0; k < 8; k++) { ts += shs[k]; tq += shq[k]; }
            float mu = ts * (1.f / 512.f);
            mu2_s = mu; iv2_s = rsqrtf(tq * (1.f / 512.f) - mu * mu + 1e-5f);
        }
        __syncthreads();
    }
    float v20 = (y0 - mu2_s) * iv2_s * s2v[tid]       + b2v[tid];
    float v21 = (y1 - mu2_s) * iv2_s * s2v[tid + 256] + b2v[tid + 256];
    g_h[rowo + tid] = v20; g_h[rowo + tid + 256] = v21;
    split_store(rowo + tid, v20);
    split_store(rowo + tid + 256, v21);

    if (do_out && i == t) {
        rowbuf[tid] = v20; rowbuf[tid + 256] = v21;
        __syncthreads();
        if (tid < NOUT) {
            const float4* wr = (const float4*)(Wout + (size_t)tid * NE);
            const float4* rb = (const float4*)rowbuf;
            float acc = 0.f;
            #pragma unroll 8
            for (int e = 0; e < 128; e++) {
                float4 aa = rb[e], ww = wr[e];
                acc += aa.x * ww.x + aa.y * ww.y + aa.z * ww.z + aa.w * ww.w;
            }
            out[((size_t)t * NB + b) * NOUT + tid] = acc + b_out[tid];
        }
    }
}

// ---- write new_h ----
__global__ void assemble_k(const float* __restrict__ hstate, float* __restrict__ outh)
{
    int idx = blockIdx.x * 256 + threadIdx.x;
    if (idx >= NB * NMEM) return;
    int b = idx / NMEM; int j = idx - b * NMEM;
    float v;
    if (j < NSTEP * NE)      v = g_h[(size_t)b * NSTEP * NE + j];
    else if (j < NMEM - 1)   v = hstate[idx];
    else                     v = (float)((int)hstate[idx] + NSTEP);
    outh[idx] = v;
}

extern "C" void kernel_launch(void* const* d_in, const int* in_sizes, int n_in,
                              void* d_out, int out_size)
{
    (void)in_sizes; (void)n_in; (void)out_size;
    const float* seq   = (const float*)d_in[0];
    const float* hst   = (const float*)d_in[1];
    const float* Win   = (const float*)d_in[2];
    const float* b_in  = (const float*)d_in[3];
    const float* Wout  = (const float*)d_in[4];
    const float* b_out = (const float*)d_in[5];
    const float* ipw   = (const float*)d_in[6];
    const float* ipb   = (const float*)d_in[7];
    const float* aow   = (const float*)d_in[8];
    const float* aob   = (const float*)d_in[9];
    const float* l1s   = (const float*)d_in[10];
    const float* l1b   = (const float*)d_in[11];
    const float* l2s   = (const float*)d_in[12];
    const float* l2b   = (const float*)d_in[13];
    const float* ffw   = (const float*)d_in[14];
    const float* ffb   = (const float*)d_in[15];
    float* out = (float*)d_out;

    cudaFuncSetAttribute(gemm_tc_k, cudaFuncAttributeMaxDynamicSharedMemorySize, GS_BYTES);

    float *pX, *pqkv, *ptmp, *ptmp2, *ph;
    bf16 *phh, *phl, *pah, *pal, *psh, *psl, *pwh, *pwl;
    cudaGetSymbolAddress((void**)&pX,    g_X);
    cudaGetSymbolAddress((void**)&pqkv,  g_qkv);
    cudaGetSymbolAddress((void**)&ptmp,  g_tmp);
    cudaGetSymbolAddress((void**)&ptmp2, g_tmp2);
    cudaGetSymbolAddress((void**)&ph,    g_h);
    cudaGetSymbolAddress((void**)&phh,   g_hh);
    cudaGetSymbolAddress((void**)&phl,   g_hl);
    cudaGetSymbolAddress((void**)&pah,   g_ah);
    cudaGetSymbolAddress((void**)&pal,   g_al);
    cudaGetSymbolAddress((void**)&psh,   g_sh);
    cudaGetSymbolAddress((void**)&psl,   g_sl);
    cudaGetSymbolAddress((void**)&pwh,   g_wh);
    cudaGetSymbolAddress((void**)&pwl,   g_wl);

    conv_all_k<<<512, 256>>>(Win, ipw, aow, ffw, seq);

    // X = seq @ Win^T + b_in (M=2048 contiguous, N=512, K=256) + scatter(0) fused
    gemm_tc_k<<<dim3(NE / 64, (NSTEP * NB) / 64), 256, GS_BYTES>>>(
        psh, psl, pwh + OFF_WIN, pwl + OFF_WIN, b_in, pX,
        NE, NIN, NSTEP * NB, 0, 0, EP_SC0, nullptr, nullptr, nullptr, nullptr);

    for (int t = 0; t < NSTEP; t++) {
        int Lq = t + 1;
        int mt = (NB * Lq) / 64;      // 2*Lq

        for (int l = 0; l < NLAY; l++) {
            gemm_tc_k<<<dim3(3 * NE / 64, mt), 256, GS_BYTES>>>(
                phh, phl, pwh + OFF_IPW + (size_t)l * 3 * NE * NE,
                pwl + OFF_IPW + (size_t)l * 3 * NE * NE,
                ipb + l * 3 * NE, pqkv, 3 * NE, NE, Lq, NSTEP, NSTEP,
                EP_NONE, nullptr, nullptr, nullptr, nullptr);
            attn_k<<<NB * NH, 256>>>(Lq);
            gemm_tc_k<<<dim3(NE / 64, mt), 256, GS_BYTES>>>(
                pah, pal, pwh + OFF_AOW + (size_t)l * NE * NE,
                pwl + OFF_AOW + (size_t)l * NE * NE,
                aob + l * NE, ptmp, NE, NE, Lq, NSTEP, NSTEP,
                EP_NONE, nullptr, nullptr, nullptr, nullptr);
            // FF with inline LN1: A = LN1(g_h + proj)
            gemm_tc_k<<<dim3(NE / 64, mt), 256, GS_BYTES>>>(
                phh, phl, pwh + OFF_FFW + (size_t)l * NE * NE,
                pwl + OFF_FFW + (size_t)l * NE * NE,
                ffb + l * NE, ptmp2, NE, NE, Lq, NSTEP, NSTEP,
                EP_LNA, l1s + l * NE, l1b + l * NE, ph, ptmp);
            // LN2 (recomputes LN1 chain); fused outproj (+scatter) on l==1
            int do_out = (l == 1) ? 1 : 0;
            int do_sc  = (l == 1 && t + 1 < NSTEP) ? 1 : 0;
            ln2_k<<<NB * Lq + (do_sc ? 64 : 0), 256>>>(
                l1s + l * NE, l1b + l * NE, l2s + l * NE, l2b + l * NE,
                ptmp, ptmp2, Lq, t, do_out, Wout, b_out, out);
        }
    }

    assemble_k<<<(NB * NMEM + 255) / 256, 256>>>(hst, out + NSTEP * NB * NOUT);
}